// round 6
// baseline (speedup 1.0000x reference)
#include <cuda_runtime.h>
#include <math.h>

// Shapes (fixed for this problem)
#define NB 16
#define CI 64
#define CO 64
#define HH 256
#define WW 256
#define M0 32
#define M1 32

// Scratch (device globals; no allocation allowed in kernel_launch)
__device__ __align__(256) float g_Xw [(size_t)NB*CI*HH*M1*2]; // 67 MB  [b][i][h][l]{re,im}
__device__ __align__(256) float g_Xm [(size_t)NB*CI*M0*M1*2]; // 8.4 MB [b][i][k*32+l]{re,im}
__device__ __align__(256) float g_Yb [(size_t)NB*CO*M0*M1*2]; // 8.4 MB [b][o][k*32+l]{re,im}
__device__ __align__(256) float g_Z  [(size_t)NB*CO*HH*M1*2]; // 67 MB  [b][o][h][l]{re,im}
__device__ __align__(256) float g_Tfwd[WW*M1*2];              // forward DFT-w matrix [w][2l|2l+1]
__device__ __align__(256) float g_Tinv[M1*2*WW];              // inverse DFT-w matrix [2l|2l+1][w]
__device__ __align__(256) float g_gamma[NB*CO];
__device__ __align__(256) float g_beta [NB*CO];

__device__ __forceinline__ float gelu_tanh(float x) {
    float u = 0.7978845608028654f * (x + 0.044715f * x * x * x);
    float t;
    asm("tanh.approx.f32 %0, %1;" : "=f"(t) : "f"(u));
    return 0.5f * x * (1.0f + t);
}

// ---------------------------------------------------------------------------
// Twiddle tables. Phase reduced mod 256 in integers (exact).
// ---------------------------------------------------------------------------
__global__ __launch_bounds__(256) void init_tables() {
    int p = blockIdx.x * blockDim.x + threadIdx.x;   // 0..8191
    if (p >= 8192) return;
    const float TWO_PI = 6.283185307179586f;
    // Forward: Tfwd[w][2l] = cos(2*pi*l*w/256), Tfwd[w][2l+1] = -sin(...)
    {
        int w = p >> 5, l = p & 31;
        int m = (w * l) & 255;
        float s, c; sincosf(TWO_PI * (float)m * (1.0f/256.0f), &s, &c);
        g_Tfwd[w*64 + 2*l    ] =  c;
        g_Tfwd[w*64 + 2*l + 1] = -s;
    }
    // Inverse (real output), full ortho norm (1/256 * 1/256) folded here.
    {
        const float norm = 1.0f / 65536.0f;
        int l = p >> 8, w = p & 255;                 // l<32, w<256
        int m = (l * w) & 255;
        float s, c; sincosf(TWO_PI * (float)m * (1.0f/256.0f), &s, &c);
        g_Tinv[(2*l  )*WW + w] = norm * (l ? 2.0f : 1.0f) * c;
        g_Tinv[(2*l+1)*WW + w] = l ? (-2.0f * norm * s) : 0.0f;
    }
}

// ---------------------------------------------------------------------------
// FiLM: h = silu(t_emb @ W1 + b1); gb = h @ W2 + b2; gamma/beta = split(gb)
// ---------------------------------------------------------------------------
__global__ __launch_bounds__(256) void filmK(const float* __restrict__ t_emb,
                                             const float* __restrict__ w1,
                                             const float* __restrict__ b1,
                                             const float* __restrict__ w2,
                                             const float* __restrict__ b2) {
    __shared__ float tsh[NB*CI];
    __shared__ float hsh[NB*CI];
    int tid = threadIdx.x;
    for (int p = tid; p < NB*CI; p += 256) tsh[p] = t_emb[p];
    __syncthreads();
    for (int p = tid; p < NB*CI; p += 256) {
        int b = p >> 6, j = p & 63;
        float s = b1[j];
        for (int i = 0; i < CI; i++) s += tsh[(b<<6)+i] * w1[i*CI + j];
        hsh[p] = s / (1.0f + expf(-s));              // silu
    }
    __syncthreads();
    for (int p = tid; p < NB*2*CO; p += 256) {
        int b = p >> 7, j = p & 127;
        float s = b2[j];
        for (int i = 0; i < CI; i++) s += hsh[(b<<6)+i] * w2[i*(2*CO) + j];
        if (j < CO) g_gamma[(b<<6)+j] = s;
        else        g_beta [(b<<6)+j-CO] = s;
    }
}

// ---------------------------------------------------------------------------
// Stage A (specialized GEMM): Xw[b,i,h,:] = x[b,i,h,:] @ Tfwd  (K=256, N=64)
// One block per (b,h). x slice transposed into smem [w][i] (pad 68);
// Tfwd fully resident. Thread = (i-quad, l-quad): 16 acc, 2 LDS.128 / 16 FFMA.
// ---------------------------------------------------------------------------
__global__ __launch_bounds__(256) void stageA2(const float* __restrict__ x) {
    extern __shared__ float sm[];
    float* xs = sm;                  // [256][68]
    float* tf = sm + 256*68;         // [256][64]
    int tid = threadIdx.x;
    int b = blockIdx.x >> 8;
    int h = blockIdx.x & 255;

    // Load Tfwd (16384 floats) coalesced
    for (int p = tid; p < 4096; p += 256)
        *(float4*)&tf[p << 2] = *(const float4*)&g_Tfwd[p << 2];
    // Load x[b, :, h, :] (64 rows x 256), transpose into xs[w][i]
    size_t xrow = (size_t)b * CI * HH * WW + (size_t)h * WW;
    for (int p = tid; p < 4096; p += 256) {
        int i  = p >> 6;
        int w4 = (p & 63) << 2;
        float4 v = *(const float4*)&x[xrow + (size_t)i * HH * WW + w4];
        xs[(w4+0)*68 + i] = v.x;
        xs[(w4+1)*68 + i] = v.y;
        xs[(w4+2)*68 + i] = v.z;
        xs[(w4+3)*68 + i] = v.w;
    }
    __syncthreads();

    int i0 = (tid >> 4) << 2;        // 16 i-groups
    int l0 = (tid & 15) << 2;        // 16 l-groups
    float acc[4][4];
#pragma unroll
    for (int r = 0; r < 4; r++)
#pragma unroll
        for (int c = 0; c < 4; c++) acc[r][c] = 0.0f;

#pragma unroll 4
    for (int k = 0; k < 256; k++) {
        float4 a = *(float4*)&xs[k*68 + i0];
        float4 t = *(float4*)&tf[k*64 + l0];
        acc[0][0] += a.x*t.x; acc[0][1] += a.x*t.y; acc[0][2] += a.x*t.z; acc[0][3] += a.x*t.w;
        acc[1][0] += a.y*t.x; acc[1][1] += a.y*t.y; acc[1][2] += a.y*t.z; acc[1][3] += a.y*t.w;
        acc[2][0] += a.z*t.x; acc[2][1] += a.z*t.y; acc[2][2] += a.z*t.z; acc[2][3] += a.z*t.w;
        acc[3][0] += a.w*t.x; acc[3][1] += a.w*t.y; acc[3][2] += a.w*t.z; acc[3][3] += a.w*t.w;
    }
#pragma unroll
    for (int r = 0; r < 4; r++) {
        size_t idx = ((size_t)(b*64 + i0 + r) * 256 + h) * 64 + l0;
        *(float4*)&g_Xw[idx] = make_float4(acc[r][0], acc[r][1], acc[r][2], acc[r][3]);
    }
}

// ---------------------------------------------------------------------------
// Stage B: Xm[b,i,k,l] = sum_h Xw[b,i,h,l] * e^{-2*pi*i*k*h/256}
// ---------------------------------------------------------------------------
__global__ __launch_bounds__(256) void stageB() {
    __shared__ float2 tw[256];
    int tid = threadIdx.x;
    { float s, c; sincosf(6.283185307179586f * (float)tid * (1.0f/256.0f), &s, &c);
      tw[tid] = make_float2(c, s); }
    __syncthreads();
    int blk = blockIdx.x;                             // b*64+i
    const float2* Xp = (const float2*)(g_Xw) + (size_t)blk * HH * M1;
    int l  = tid & 31;
    int k0 = tid >> 5;
    float2 acc[4];
    int mt[4];
#pragma unroll
    for (int t = 0; t < 4; t++) { acc[t] = make_float2(0.f, 0.f); mt[t] = 0; }
    for (int h = 0; h < HH; h++) {
        float2 xv = Xp[h*M1 + l];
#pragma unroll
        for (int t = 0; t < 4; t++) {
            float2 e = tw[mt[t]];
            acc[t].x += xv.x*e.x + xv.y*e.y;          // (xr+ixi)*(c - i s)
            acc[t].y += xv.y*e.x - xv.x*e.y;
            mt[t] = (mt[t] + k0 + (t << 3)) & 255;
        }
    }
    float2* Om = (float2*)g_Xm + (size_t)blk * (M0*M1);
#pragma unroll
    for (int t = 0; t < 4; t++) {
        int k = k0 + (t << 3);
        Om[k*M1 + l] = acc[t];
    }
}

// ---------------------------------------------------------------------------
// Mode mix + FiLM gamma folding:
// Y[b,o,kl] = (1+gamma[b,o]) * sum_i Xm[b,i,kl] * (wr + i*wi)[i,o,kl]
// ---------------------------------------------------------------------------
__global__ __launch_bounds__(256) void mixK(const float* __restrict__ wr,
                                            const float* __restrict__ wi) {
    __shared__ float2 Wsh[CI*CO];    // 32 KB
    __shared__ float2 Xsh[NB*CI];    //  8 KB
    int kl = blockIdx.x;
    int tid = threadIdx.x;
    for (int p = tid; p < CI*CO; p += 256)
        Wsh[p] = make_float2(wr[(size_t)p*1024 + kl], wi[(size_t)p*1024 + kl]);
    for (int p = tid; p < NB*CI; p += 256)
        Xsh[p] = ((const float2*)g_Xm)[(size_t)p*1024 + kl];
    __syncthreads();
#pragma unroll
    for (int q = 0; q < 4; q++) {
        int idx = tid + q*256;                        // b*64+o
        int b = idx >> 6, o = idx & 63;
        float yr = 0.f, yi = 0.f;
#pragma unroll 8
        for (int i = 0; i < CI; i++) {
            float2 xv = Xsh[(b << 6) + i];
            float2 wv = Wsh[(i << 6) + o];
            yr += xv.x*wv.x - xv.y*wv.y;
            yi += xv.x*wv.y + xv.y*wv.x;
        }
        float g = 1.0f + g_gamma[idx];
        ((float2*)g_Yb)[(size_t)idx*1024 + kl] = make_float2(g*yr, g*yi);
    }
}

// ---------------------------------------------------------------------------
// Stage C: Z[b,o,h,l] = sum_{k<32} Y[b,o,k,l] * e^{+2*pi*i*k*h/256}
// ---------------------------------------------------------------------------
__global__ __launch_bounds__(256) void stageC() {
    __shared__ float2 tw[256];
    int tid = threadIdx.x;
    { float s, c; sincosf(6.283185307179586f * (float)tid * (1.0f/256.0f), &s, &c);
      tw[tid] = make_float2(c, s); }
    __syncthreads();
    int blk = blockIdx.x;                             // b*64+o
    const float2* Yp = (const float2*)g_Yb + (size_t)blk * (M0*M1);
    int l  = tid & 31;
    int h0 = tid >> 5;
    float2 acc[32];
#pragma unroll
    for (int t = 0; t < 32; t++) acc[t] = make_float2(0.f, 0.f);
    for (int k = 0; k < M0; k++) {
        float2 yv = Yp[k*M1 + l];
        int mm = (k * h0) & 255;
        int st = (k << 3) & 255;
#pragma unroll
        for (int t = 0; t < 32; t++) {
            float2 e = tw[mm];
            acc[t].x += yv.x*e.x - yv.y*e.y;
            acc[t].y += yv.x*e.y + yv.y*e.x;
            mm = (mm + st) & 255;
        }
    }
    float2* Zp = (float2*)g_Z + (size_t)blk * HH * M1;
#pragma unroll
    for (int t = 0; t < 32; t++)
        Zp[(h0 + (t << 3))*M1 + l] = acc[t];
}

// ---------------------------------------------------------------------------
// Fused inverse-w DFT + FiLM beta + bypass 1x1 conv + GELU.
// One block per (b,h); thread owns column w=tid; acc[64] over o shared by
// both GEMMs (gamma already folded into Z via mixK).
//   out[b,o,h,w] = gelu( sum_l' ZZ[l'][o]*Tinv[l'][w]
//                        + sum_i bw[o][i]*x[b,i,h,w] + beta[b,o] + bb[o] )
// ---------------------------------------------------------------------------
#define ZPAD 68
__global__ __launch_bounds__(256, 2) void specfinalK(const float* __restrict__ x,
                                                     const float* __restrict__ bw,
                                                     const float* __restrict__ bb,
                                                     float* __restrict__ out) {
    extern __shared__ float sm[];
    float* tinv_s = sm;                       // [64][256]  16384
    float* zzs    = sm + 16384;               // [64][ZPAD]  4352
    float* bwsh   = zzs + 64*ZPAD;            // [64][64]    4096
    float* beta_s = bwsh + 4096;              // [64]
    int tid = threadIdx.x;
    int b = blockIdx.x >> 8;
    int h = blockIdx.x & 255;

    for (int p = tid; p < 4096; p += 256)
        *(float4*)&tinv_s[p << 2] = *(const float4*)&g_Tinv[p << 2];
    for (int p = tid; p < 1024; p += 256)
        *(float4*)&bwsh[p << 2] = *(const float4*)&bw[p << 2];
    // ZZ fill: read Z[b,o,h,l] (coalesced per o), store transposed [l'][o]
    for (int p = tid; p < 2048; p += 256) {
        int o = p >> 5, l = p & 31;
        float2 v = ((const float2*)g_Z)[((size_t)(b*64 + o) * 256 + h) * 32 + l];
        zzs[(2*l  )*ZPAD + o] = v.x;
        zzs[(2*l+1)*ZPAD + o] = v.y;
    }
    if (tid < 64) beta_s[tid] = g_beta[b*64 + tid] + bb[tid];
    __syncthreads();

    float acc[64];
#pragma unroll
    for (int o = 0; o < 64; o++) acc[o] = 0.0f;

    // Spectral part: acc[o] += ZZ[l'][o] * Tinv[l'][w]
    const float* tp = tinv_s + tid;
#pragma unroll 2
    for (int lp = 0; lp < 64; lp++) {
        float tv = tp[lp << 8];
        const float* zr = zzs + lp * ZPAD;
#pragma unroll
        for (int og = 0; og < 16; og++) {
            float4 z = *(const float4*)&zr[og << 2];
            acc[4*og+0] += z.x * tv;
            acc[4*og+1] += z.y * tv;
            acc[4*og+2] += z.z * tv;
            acc[4*og+3] += z.w * tv;
        }
    }

    // Bypass part: acc[o] += sum_i bw[o][i] * x[b,i,h,w]
    size_t xb = (size_t)b * CI * HH * WW + (size_t)h * WW + tid;
    for (int i = 0; i < CI; i += 4) {
        float x0 = x[xb + (size_t)(i+0) * HH * WW];
        float x1 = x[xb + (size_t)(i+1) * HH * WW];
        float x2 = x[xb + (size_t)(i+2) * HH * WW];
        float x3 = x[xb + (size_t)(i+3) * HH * WW];
#pragma unroll
        for (int o = 0; o < 64; o++) {
            float4 w4 = *(const float4*)&bwsh[(o << 6) + i];
            acc[o] += w4.x*x0 + w4.y*x1 + w4.z*x2 + w4.w*x3;
        }
    }

    size_t ob = (size_t)b * CO * HH * WW + (size_t)h * WW + tid;
#pragma unroll 8
    for (int o = 0; o < 64; o++)
        out[ob + (size_t)o * HH * WW] = gelu_tanh(acc[o] + beta_s[o]);
}

// ---------------------------------------------------------------------------
extern "C" void kernel_launch(void* const* d_in, const int* in_sizes, int n_in,
                              void* d_out, int out_size) {
    const float* x      = (const float*)d_in[0];
    const float* t_emb  = (const float*)d_in[1];
    const float* w_real = (const float*)d_in[2];
    const float* w_imag = (const float*)d_in[3];
    const float* fw1    = (const float*)d_in[4];
    const float* fb1    = (const float*)d_in[5];
    const float* fw2    = (const float*)d_in[6];
    const float* fb2    = (const float*)d_in[7];
    const float* bw     = (const float*)d_in[8];
    const float* bb     = (const float*)d_in[9];
    float* out = (float*)d_out;

    const int smemA = (256*68 + 256*64) * sizeof(float);            // 135168
    const int smemF = (16384 + 64*ZPAD + 4096 + 64) * sizeof(float); // 99584
    cudaFuncSetAttribute(stageA2,    cudaFuncAttributeMaxDynamicSharedMemorySize, smemA);
    cudaFuncSetAttribute(specfinalK, cudaFuncAttributeMaxDynamicSharedMemorySize, smemF);

    init_tables<<<32, 256>>>();
    filmK<<<1, 256>>>(t_emb, fw1, fb1, fw2, fb2);
    stageA2<<<NB*HH, 256, smemA>>>(x);
    stageB<<<NB*CI, 256>>>();
    mixK<<<M0*M1, 256>>>(w_real, w_imag);
    stageC<<<NB*CO, 256>>>();
    specfinalK<<<NB*HH, 256, smemF>>>(x, bw, bb, out);
}

// round 7
// speedup vs baseline: 1.1770x; 1.1770x over previous
#include <cuda_runtime.h>
#include <math.h>

// Shapes (fixed for this problem)
#define NB 16
#define CI 64
#define CO 64
#define HH 256
#define WW 256
#define M0 32
#define M1 32

// Scratch (device globals; no allocation allowed in kernel_launch)
__device__ __align__(256) float g_Xw [(size_t)NB*CI*HH*M1*2]; // 67 MB  [b][i][h][l]{re,im}
__device__ __align__(256) float g_Xm [(size_t)NB*CI*M0*M1*2]; // 8.4 MB [b][i][k*32+l]{re,im}
__device__ __align__(256) float g_Yb [(size_t)NB*CO*M0*M1*2]; // 8.4 MB [b][o][k*32+l]{re,im}
__device__ __align__(256) float g_Z  [(size_t)NB*CO*HH*M1*2]; // 67 MB  [b][o][h][l]{re,im}
__device__ __align__(256) float g_Tfwd[WW*M1*2];              // forward DFT-w matrix [w][2l|2l+1]
__device__ __align__(256) float g_Tinv[M1*2*WW];              // inverse DFT-w matrix [2l|2l+1][w]
__device__ __align__(256) float g_gamma[NB*CO];
__device__ __align__(256) float g_beta [NB*CO];

__device__ __forceinline__ float gelu_tanh(float x) {
    float u = 0.7978845608028654f * (x + 0.044715f * x * x * x);
    float t;
    asm("tanh.approx.f32 %0, %1;" : "=f"(t) : "f"(u));
    return 0.5f * x * (1.0f + t);
}

// ---------------------------------------------------------------------------
// Twiddle tables. Phase reduced mod 256 in integers (exact).
// ---------------------------------------------------------------------------
__global__ __launch_bounds__(256) void init_tables() {
    int p = blockIdx.x * blockDim.x + threadIdx.x;   // 0..8191
    if (p >= 8192) return;
    const float TWO_PI = 6.283185307179586f;
    // Forward: Tfwd[w][2l] = cos(2*pi*l*w/256), Tfwd[w][2l+1] = -sin(...)
    {
        int w = p >> 5, l = p & 31;
        int m = (w * l) & 255;
        float s, c; sincosf(TWO_PI * (float)m * (1.0f/256.0f), &s, &c);
        g_Tfwd[w*64 + 2*l    ] =  c;
        g_Tfwd[w*64 + 2*l + 1] = -s;
    }
    // Inverse (real output), full ortho norm (1/256 * 1/256) folded here.
    {
        const float norm = 1.0f / 65536.0f;
        int l = p >> 8, w = p & 255;                 // l<32, w<256
        int m = (l * w) & 255;
        float s, c; sincosf(TWO_PI * (float)m * (1.0f/256.0f), &s, &c);
        g_Tinv[(2*l  )*WW + w] = norm * (l ? 2.0f : 1.0f) * c;
        g_Tinv[(2*l+1)*WW + w] = l ? (-2.0f * norm * s) : 0.0f;
    }
}

// ---------------------------------------------------------------------------
// FiLM: h = silu(t_emb @ W1 + b1); gb = h @ W2 + b2; gamma/beta = split(gb)
// ---------------------------------------------------------------------------
__global__ __launch_bounds__(256) void filmK(const float* __restrict__ t_emb,
                                             const float* __restrict__ w1,
                                             const float* __restrict__ b1,
                                             const float* __restrict__ w2,
                                             const float* __restrict__ b2) {
    __shared__ float tsh[NB*CI];
    __shared__ float hsh[NB*CI];
    int tid = threadIdx.x;
    for (int p = tid; p < NB*CI; p += 256) tsh[p] = t_emb[p];
    __syncthreads();
    for (int p = tid; p < NB*CI; p += 256) {
        int b = p >> 6, j = p & 63;
        float s = b1[j];
        for (int i = 0; i < CI; i++) s += tsh[(b<<6)+i] * w1[i*CI + j];
        hsh[p] = s / (1.0f + expf(-s));              // silu
    }
    __syncthreads();
    for (int p = tid; p < NB*2*CO; p += 256) {
        int b = p >> 7, j = p & 127;
        float s = b2[j];
        for (int i = 0; i < CI; i++) s += hsh[(b<<6)+i] * w2[i*(2*CO) + j];
        if (j < CO) g_gamma[(b<<6)+j] = s;
        else        g_beta [(b<<6)+j-CO] = s;
    }
}

// ---------------------------------------------------------------------------
// Generic tiled SGEMM: C[M,N] = A[M,K] * B[K,N]. BM=BN=64, BK=32, 256 thr,
// 4x4 micro-tile, float4 smem reads. (Proven in R5 baseline.)
// ---------------------------------------------------------------------------
__global__ __launch_bounds__(256) void gemm64(const float* __restrict__ A,
                                              const float* __restrict__ Bm,
                                              float* __restrict__ C,
                                              int M, int K, int N) {
    __shared__ float As[32][68];   // [k][r]
    __shared__ float Bs[32][64];   // [k][c]
    int row0 = blockIdx.x * 64;
    int col0 = blockIdx.y * 64;
    int tid = threadIdx.x;
    int tx = tid & 15, ty = tid >> 4;
    float acc[4][4];
#pragma unroll
    for (int i = 0; i < 4; i++)
#pragma unroll
        for (int j = 0; j < 4; j++) acc[i][j] = 0.0f;

    for (int k0 = 0; k0 < K; k0 += 32) {
#pragma unroll
        for (int v = 0; v < 2; v++) {
            int lin = tid + v*256;                    // 0..511 float4 slots
            int r  = lin >> 3;
            int kk = (lin & 7) << 2;
            float4 a = *(const float4*)(A + (size_t)(row0 + r)*K + k0 + kk);
            As[kk+0][r] = a.x; As[kk+1][r] = a.y; As[kk+2][r] = a.z; As[kk+3][r] = a.w;
            int kb = lin >> 4;
            int c  = (lin & 15) << 2;
            *(float4*)&Bs[kb][c] = *(const float4*)(Bm + (size_t)(k0 + kb)*N + col0 + c);
        }
        __syncthreads();
#pragma unroll
        for (int k = 0; k < 32; k++) {
            float4 a = *(float4*)&As[k][ty << 2];
            float4 b = *(float4*)&Bs[k][tx << 2];
            acc[0][0] += a.x*b.x; acc[0][1] += a.x*b.y; acc[0][2] += a.x*b.z; acc[0][3] += a.x*b.w;
            acc[1][0] += a.y*b.x; acc[1][1] += a.y*b.y; acc[1][2] += a.y*b.z; acc[1][3] += a.y*b.w;
            acc[2][0] += a.z*b.x; acc[2][1] += a.z*b.y; acc[2][2] += a.z*b.z; acc[2][3] += a.z*b.w;
            acc[3][0] += a.w*b.x; acc[3][1] += a.w*b.y; acc[3][2] += a.w*b.z; acc[3][3] += a.w*b.w;
        }
        __syncthreads();
    }
#pragma unroll
    for (int i = 0; i < 4; i++) {
        float4 v = make_float4(acc[i][0], acc[i][1], acc[i][2], acc[i][3]);
        *(float4*)(C + (size_t)(row0 + (ty<<2) + i)*N + col0 + (tx<<2)) = v;
    }
}

// ---------------------------------------------------------------------------
// Stage B: Xm[b,i,k,l] = sum_h Xw[b,i,h,l] * e^{-2*pi*i*k*h/256}
// ---------------------------------------------------------------------------
__global__ __launch_bounds__(256) void stageB() {
    __shared__ float2 tw[256];
    int tid = threadIdx.x;
    { float s, c; sincosf(6.283185307179586f * (float)tid * (1.0f/256.0f), &s, &c);
      tw[tid] = make_float2(c, s); }
    __syncthreads();
    int blk = blockIdx.x;                             // b*64+i
    const float2* Xp = (const float2*)(g_Xw) + (size_t)blk * HH * M1;
    int l  = tid & 31;
    int k0 = tid >> 5;
    float2 acc[4];
    int mt[4];
#pragma unroll
    for (int t = 0; t < 4; t++) { acc[t] = make_float2(0.f, 0.f); mt[t] = 0; }
    for (int h = 0; h < HH; h++) {
        float2 xv = Xp[h*M1 + l];
#pragma unroll
        for (int t = 0; t < 4; t++) {
            float2 e = tw[mt[t]];
            acc[t].x += xv.x*e.x + xv.y*e.y;          // (xr+ixi)*(c - i s)
            acc[t].y += xv.y*e.x - xv.x*e.y;
            mt[t] = (mt[t] + k0 + (t << 3)) & 255;
        }
    }
    float2* Om = (float2*)g_Xm + (size_t)blk * (M0*M1);
#pragma unroll
    for (int t = 0; t < 4; t++) {
        int k = k0 + (t << 3);
        Om[k*M1 + l] = acc[t];
    }
}

// ---------------------------------------------------------------------------
// Mode mix + FiLM gamma folding:
// Y[b,o,kl] = (1+gamma[b,o]) * sum_i Xm[b,i,kl] * (wr + i*wi)[i,o,kl]
// ---------------------------------------------------------------------------
__global__ __launch_bounds__(256) void mixK(const float* __restrict__ wr,
                                            const float* __restrict__ wi) {
    __shared__ float2 Wsh[CI*CO];    // 32 KB
    __shared__ float2 Xsh[NB*CI];    //  8 KB
    int kl = blockIdx.x;
    int tid = threadIdx.x;
    for (int p = tid; p < CI*CO; p += 256)
        Wsh[p] = make_float2(wr[(size_t)p*1024 + kl], wi[(size_t)p*1024 + kl]);
    for (int p = tid; p < NB*CI; p += 256)
        Xsh[p] = ((const float2*)g_Xm)[(size_t)p*1024 + kl];
    __syncthreads();
#pragma unroll
    for (int q = 0; q < 4; q++) {
        int idx = tid + q*256;                        // b*64+o
        int b = idx >> 6, o = idx & 63;
        float yr = 0.f, yi = 0.f;
#pragma unroll 8
        for (int i = 0; i < CI; i++) {
            float2 xv = Xsh[(b << 6) + i];
            float2 wv = Wsh[(i << 6) + o];
            yr += xv.x*wv.x - xv.y*wv.y;
            yi += xv.x*wv.y + xv.y*wv.x;
        }
        float g = 1.0f + g_gamma[idx];
        ((float2*)g_Yb)[(size_t)idx*1024 + kl] = make_float2(g*yr, g*yi);
    }
}

// ---------------------------------------------------------------------------
// Stage C: Z[b,o,h,l] = sum_{k<32} Y[b,o,k,l] * e^{+2*pi*i*k*h/256}
// ---------------------------------------------------------------------------
__global__ __launch_bounds__(256) void stageC() {
    __shared__ float2 tw[256];
    int tid = threadIdx.x;
    { float s, c; sincosf(6.283185307179586f * (float)tid * (1.0f/256.0f), &s, &c);
      tw[tid] = make_float2(c, s); }
    __syncthreads();
    int blk = blockIdx.x;                             // b*64+o
    const float2* Yp = (const float2*)g_Yb + (size_t)blk * (M0*M1);
    int l  = tid & 31;
    int h0 = tid >> 5;
    float2 acc[32];
#pragma unroll
    for (int t = 0; t < 32; t++) acc[t] = make_float2(0.f, 0.f);
    for (int k = 0; k < M0; k++) {
        float2 yv = Yp[k*M1 + l];
        int mm = (k * h0) & 255;
        int st = (k << 3) & 255;
#pragma unroll
        for (int t = 0; t < 32; t++) {
            float2 e = tw[mm];
            acc[t].x += yv.x*e.x - yv.y*e.y;
            acc[t].y += yv.x*e.y + yv.y*e.x;
            mm = (mm + st) & 255;
        }
    }
    float2* Zp = (float2*)g_Z + (size_t)blk * HH * M1;
#pragma unroll
    for (int t = 0; t < 32; t++)
        Zp[(h0 + (t << 3))*M1 + l] = acc[t];
}

// ---------------------------------------------------------------------------
// Fused inverse-w DFT + FiLM beta + bypass 1x1 conv + GELU.
// One block per (b,h); thread owns column w=tid; acc[64] over o shared by
// both GEMMs (gamma already folded into Z via mixK).
// NOTE: no min-blocks clause — R6's (256,2) capped regs at 128 and spilled
// the 64-deep accumulator file. Occupancy is 2 CTAs/SM via 99.5KB smem.
// ---------------------------------------------------------------------------
#define ZPAD 68
__global__ __launch_bounds__(256) void specfinalK(const float* __restrict__ x,
                                                  const float* __restrict__ bw,
                                                  const float* __restrict__ bb,
                                                  float* __restrict__ out) {
    extern __shared__ float sm[];
    float* tinv_s = sm;                       // [64][256]  16384
    float* zzs    = sm + 16384;               // [64][ZPAD]  4352
    float* bwsh   = zzs + 64*ZPAD;            // [64][64]    4096
    float* beta_s = bwsh + 4096;              // [64]
    int tid = threadIdx.x;
    int b = blockIdx.x >> 8;
    int h = blockIdx.x & 255;

    for (int p = tid; p < 4096; p += 256)
        *(float4*)&tinv_s[p << 2] = *(const float4*)&g_Tinv[p << 2];
    for (int p = tid; p < 1024; p += 256)
        *(float4*)&bwsh[p << 2] = *(const float4*)&bw[p << 2];
    // ZZ fill: read Z[b,o,h,l] (coalesced per o), store transposed [l'][o]
    for (int p = tid; p < 2048; p += 256) {
        int o = p >> 5, l = p & 31;
        float2 v = ((const float2*)g_Z)[((size_t)(b*64 + o) * 256 + h) * 32 + l];
        zzs[(2*l  )*ZPAD + o] = v.x;
        zzs[(2*l+1)*ZPAD + o] = v.y;
    }
    if (tid < 64) beta_s[tid] = g_beta[b*64 + tid] + bb[tid];
    __syncthreads();

    float acc[64];
#pragma unroll
    for (int o = 0; o < 64; o++) acc[o] = 0.0f;

    // Bypass part first (LDG-latency heavy): acc[o] += sum_i bw[o][i]*x[b,i,h,w]
    // Software-pipelined x loads (MLP=8) so FFMA issue hides L2/DRAM latency.
    size_t xb = (size_t)b * CI * HH * WW + (size_t)h * WW + tid;
    float c0 = x[xb + 0*(size_t)HH*WW];
    float c1 = x[xb + 1*(size_t)HH*WW];
    float c2 = x[xb + 2*(size_t)HH*WW];
    float c3 = x[xb + 3*(size_t)HH*WW];
    for (int i = 0; i < CI; i += 4) {
        float n0, n1, n2, n3;
        if (i + 4 < CI) {
            n0 = x[xb + (size_t)(i+4) * HH * WW];
            n1 = x[xb + (size_t)(i+5) * HH * WW];
            n2 = x[xb + (size_t)(i+6) * HH * WW];
            n3 = x[xb + (size_t)(i+7) * HH * WW];
        }
#pragma unroll
        for (int o = 0; o < 64; o++) {
            float4 w4 = *(const float4*)&bwsh[(o << 6) + i];  // warp-uniform broadcast
            acc[o] += w4.x*c0 + w4.y*c1 + w4.z*c2 + w4.w*c3;
        }
        c0 = n0; c1 = n1; c2 = n2; c3 = n3;
    }

    // Spectral part: acc[o] += ZZ[l'][o] * Tinv[l'][w]
    const float* tp = tinv_s + tid;
#pragma unroll 2
    for (int lp = 0; lp < 64; lp++) {
        float tv = tp[lp << 8];
        const float* zr = zzs + lp * ZPAD;
#pragma unroll
        for (int og = 0; og < 16; og++) {
            float4 z = *(const float4*)&zr[og << 2];
            acc[4*og+0] += z.x * tv;
            acc[4*og+1] += z.y * tv;
            acc[4*og+2] += z.z * tv;
            acc[4*og+3] += z.w * tv;
        }
    }

    size_t ob = (size_t)b * CO * HH * WW + (size_t)h * WW + tid;
#pragma unroll 8
    for (int o = 0; o < 64; o++)
        out[ob + (size_t)o * HH * WW] = gelu_tanh(acc[o] + beta_s[o]);
}

// ---------------------------------------------------------------------------
extern "C" void kernel_launch(void* const* d_in, const int* in_sizes, int n_in,
                              void* d_out, int out_size) {
    const float* x      = (const float*)d_in[0];
    const float* t_emb  = (const float*)d_in[1];
    const float* w_real = (const float*)d_in[2];
    const float* w_imag = (const float*)d_in[3];
    const float* fw1    = (const float*)d_in[4];
    const float* fb1    = (const float*)d_in[5];
    const float* fw2    = (const float*)d_in[6];
    const float* fb2    = (const float*)d_in[7];
    const float* bw     = (const float*)d_in[8];
    const float* bb     = (const float*)d_in[9];
    float* out = (float*)d_out;

    float *pXw, *pTf;
    cudaGetSymbolAddress((void**)&pXw, g_Xw);
    cudaGetSymbolAddress((void**)&pTf, g_Tfwd);

    const int smemF = (16384 + 64*ZPAD + 4096 + 64) * sizeof(float); // 99584
    cudaFuncSetAttribute(specfinalK, cudaFuncAttributeMaxDynamicSharedMemorySize, smemF);

    init_tables<<<32, 256>>>();
    filmK<<<1, 256>>>(t_emb, fw1, fb1, fw2, fb2);
    // Stage A: Xw = x (262144 x 256) @ Tfwd (256 x 64)
    gemm64<<<dim3(4096, 1), 256>>>(x, pTf, pXw, NB*CI*HH, WW, 2*M1);
    stageB<<<NB*CI, 256>>>();
    mixK<<<M0*M1, 256>>>(w_real, w_imag);
    stageC<<<NB*CO, 256>>>();
    specfinalK<<<NB*HH, 256, smemF>>>(x, bw, bb, out);
}